// round 15
// baseline (speedup 1.0000x reference)
#include <cuda_runtime.h>
#include <cuda_bf16.h>
#include <mma.h>
#include <stdint.h>

using namespace nvcuda;

// Problem constants
#define BSZ 2
#define TT  1024
#define DD  768
#define KK  24
#define SS  128
#define KX  5
#define NCH (BSZ*DD)   // 1536 channels
#define NC  8          // chunks per channel
#define CL  128        // chunk length (NC*CL == TT)
#define MM  (BSZ*TT)   // 2048 GEMM rows

// Static device scratch
__device__ float g_u[NCH * TT];          // u[(b*768+d)*1024 + t]
__device__ float g_wt[DD * SS];          // folded readout weight w~[d][s]
__device__ float g_gd[DD * KX];          // folded direct taps gdir[d][j]
__device__ float g_A[SS];                // resolved decay A
__device__ float g_A128[SS];             // A^CL
__device__ float g_Bm[SS];               // resolved input map Bm
__device__ float g_hst[NCH * NC * SS];   // chunk states
__device__ __nv_bfloat16 g_xh[MM * DD];  // x hi (bf16)
__device__ __nv_bfloat16 g_xl[MM * DD];  // x lo (bf16 residual)
__device__ __nv_bfloat16 g_mh[DD * DD];  // M hi
__device__ __nv_bfloat16 g_ml[DD * DD];  // M lo

// ---------------------------------------------------------------------------
// Kernel 0: resolve A (uniform(0,1): all >= 0) vs Bm (has negatives),
// and precompute A^128 by squaring.
// ---------------------------------------------------------------------------
__global__ void resolve_kernel(const float* __restrict__ p0,
                               const float* __restrict__ p1)
{
    __shared__ int neg0;
    if (threadIdx.x == 0) neg0 = 0;
    __syncthreads();
    if (p0[threadIdx.x] < 0.f) atomicAdd(&neg0, 1);
    __syncthreads();
    const float* Ap = (neg0 > 0) ? p1 : p0;
    const float* Bp = (neg0 > 0) ? p0 : p1;
    float a = Ap[threadIdx.x];
    g_A[threadIdx.x]  = a;
    g_Bm[threadIdx.x] = Bp[threadIdx.x];
    float p = a;
#pragma unroll
    for (int i = 0; i < 7; ++i) p = p * p;   // a^128
    g_A128[threadIdx.x] = p;
}

// ---------------------------------------------------------------------------
// Kernel 1: fold weights.
// ---------------------------------------------------------------------------
__global__ void prep_kernel(const float* __restrict__ Mf,    // (24,768)
                            const float* __restrict__ C,     // (48,128)
                            const float* __restrict__ Mdir)  // (48,5)
{
    int d = blockIdx.x;
    int s = threadIdx.x;
    float acc = 0.f;
#pragma unroll
    for (int k = 0; k < KK; ++k) {
        float mf = Mf[k * DD + d];
        acc += mf * (C[k * SS + s] + C[(KK + k) * SS + s]);
    }
    g_wt[d * SS + s] = acc * g_Bm[s];
    if (s < KX) {
        float a = 0.f;
#pragma unroll
        for (int k = 0; k < KK; ++k) {
            float mf = Mf[k * DD + d];
            a += mf * (Mdir[k * KX + s] + Mdir[(KK + k) * KX + s]);
        }
        g_gd[d * KX + s] = a;
    }
}

// ---------------------------------------------------------------------------
// Kernel 1b: split x and M into bf16 hi + bf16 residual.
// ---------------------------------------------------------------------------
__global__ void convert_kernel(const float* __restrict__ x,
                               const float* __restrict__ M)
{
    int i = blockIdx.x * 256 + threadIdx.x;
    if (i < MM * DD) {
        float v = x[i];
        __nv_bfloat16 h = __float2bfloat16(v);
        g_xh[i] = h;
        g_xl[i] = __float2bfloat16(v - __bfloat162float(h));
    }
    if (i < DD * DD) {
        float v = M[i];
        __nv_bfloat16 h = __float2bfloat16(v);
        g_mh[i] = h;
        g_ml[i] = __float2bfloat16(v - __bfloat162float(h));
    }
}

// ---------------------------------------------------------------------------
// Kernel 2: tensor-core GEMM via WMMA + register-prefetch pipelining.
// u[(b,d),t] = sum_c x[m,c]*M[c,d], m = b*1024 + t.
// CTA tile 64m x 64d, BK=32, 8 warps (4m x 2n), warp tile 16x32.
// Grid 384, 3072 warps total (~19 warps/SM resident).
// ASTR=40 (80B): conflict-free ldmatrix phases on A (48 had 2-way conflicts).
// Split precision: acc = xh*mh + xh*ml + xl*mh, f32 accumulate.
// store_matrix_sync(mem_col_major, ldm=TT) writes directly transposed to g_u.
// ---------------------------------------------------------------------------
#define ASTR 40     // A smem row stride (bf16 units); 80B, conflict-free
#define BSTR 72     // B smem row stride; 144B, conflict-free

__global__ __launch_bounds__(256) void gemm_kernel()
{
    __shared__ __align__(32) __nv_bfloat16 Ah[64 * ASTR];
    __shared__ __align__(32) __nv_bfloat16 Al[64 * ASTR];
    __shared__ __align__(32) __nv_bfloat16 Bh[32 * BSTR];
    __shared__ __align__(32) __nv_bfloat16 Bl[32 * BSTR];

    const int tid = threadIdx.x;
    const int wid = tid >> 5;
    const int wm  = wid & 3;          // warp m position (4 x 16 rows)
    const int wn  = wid >> 2;         // warp n position (2 x 32 cols)

    const int m0 = blockIdx.y * 64;   // global row (b*1024 + t)
    const int d0 = blockIdx.x * 64;

    // per-thread load coordinates (1 uint4 chunk per matrix per tile)
    const int ra = tid >> 2, qa = tid & 3;    // A: 64 rows x 4 chunks
    const int rb = tid >> 3, qb = tid & 7;    // B: 32 rows x 8 chunks

    wmma::fragment<wmma::accumulator, 16, 16, 16, float> fc[2];
#pragma unroll
    for (int j = 0; j < 2; ++j)
        wmma::fill_fragment(fc[j], 0.f);

    // prologue: prefetch tile 0
    uint4 pah, pal, pbh, pbl;
    {
        const size_t a = (size_t)(m0 + ra) * DD + 0 + qa * 8;
        const size_t b = (size_t)(0 + rb) * DD + d0 + qb * 8;
        pah = *(const uint4*)&g_xh[a];
        pal = *(const uint4*)&g_xl[a];
        pbh = *(const uint4*)&g_mh[b];
        pbl = *(const uint4*)&g_ml[b];
    }

    for (int iter = 0; iter < DD / 32; ++iter) {
        // store prefetched tile into smem
        *(uint4*)&Ah[ra * ASTR + qa * 8] = pah;
        *(uint4*)&Al[ra * ASTR + qa * 8] = pal;
        *(uint4*)&Bh[rb * BSTR + qb * 8] = pbh;
        *(uint4*)&Bl[rb * BSTR + qb * 8] = pbl;
        __syncthreads();

        // prefetch next tile (in flight during compute below)
        if (iter + 1 < DD / 32) {
            const int cn = (iter + 1) * 32;
            const size_t a = (size_t)(m0 + ra) * DD + cn + qa * 8;
            const size_t b = (size_t)(cn + rb) * DD + d0 + qb * 8;
            pah = *(const uint4*)&g_xh[a];
            pal = *(const uint4*)&g_xl[a];
            pbh = *(const uint4*)&g_mh[b];
            pbl = *(const uint4*)&g_ml[b];
        }

        // compute on current smem tile
#pragma unroll
        for (int kc = 0; kc < 2; ++kc) {
            wmma::fragment<wmma::matrix_a, 16, 16, 16, __nv_bfloat16, wmma::row_major> fah, fal;
            wmma::fragment<wmma::matrix_b, 16, 16, 16, __nv_bfloat16, wmma::row_major> fbh[2], fbl[2];
            {
                const __nv_bfloat16* pa = &Ah[(wm * 16) * ASTR + kc * 16];
                const __nv_bfloat16* pl = &Al[(wm * 16) * ASTR + kc * 16];
                wmma::load_matrix_sync(fah, pa, ASTR);
                wmma::load_matrix_sync(fal, pl, ASTR);
            }
#pragma unroll
            for (int j = 0; j < 2; ++j) {
                const __nv_bfloat16* pb = &Bh[(kc * 16) * BSTR + wn * 32 + j * 16];
                const __nv_bfloat16* pl = &Bl[(kc * 16) * BSTR + wn * 32 + j * 16];
                wmma::load_matrix_sync(fbh[j], pb, BSTR);
                wmma::load_matrix_sync(fbl[j], pl, BSTR);
            }
#pragma unroll
            for (int j = 0; j < 2; ++j) {
                wmma::mma_sync(fc[j], fah, fbh[j], fc[j]);
                wmma::mma_sync(fc[j], fah, fbl[j], fc[j]);
                wmma::mma_sync(fc[j], fal, fbh[j], fc[j]);
            }
        }
        __syncthreads();
    }

    // store transposed directly: col-major with ldm=TT puts element (m,n) at
    // dst[n*TT + m]  ->  g_u[(b*DD + d)*TT + t]
    const int mb = m0 + wm * 16;
    const int b  = mb >> 10;
    const int tb = mb & 1023;
#pragma unroll
    for (int j = 0; j < 2; ++j) {
        int d = d0 + wn * 32 + j * 16;
        float* dst = &g_u[((size_t)b * DD + d) * TT + tb];
        wmma::store_matrix_sync(dst, fc[j], TT, wmma::mem_col_major);
    }
}

// ---------------------------------------------------------------------------
// Kernel 3a (pass 1): local chunk end-states.
// Chunk 7's end state is never consumed by combine -> early exit.
// ---------------------------------------------------------------------------
__global__ __launch_bounds__(128) void state_kernel()
{
    const int w    = threadIdx.x >> 5;
    const int lane = threadIdx.x & 31;
    const int gw   = blockIdx.x * 4 + w;
    const int ch   = gw >> 3;
    const int c    = gw & 7;
    if (c == NC - 1) return;   // end state of last chunk unused

    const float* uc = g_u + (size_t)ch * TT + c * CL;
    const float a0 = g_A[lane],      a1 = g_A[lane + 32],
                a2 = g_A[lane + 64], a3 = g_A[lane + 96];

    float h0 = 0.f, h1 = 0.f, h2 = 0.f, h3 = 0.f;
#pragma unroll
    for (int r = 0; r < CL / 32; ++r) {
        const float uv = uc[r * 32 + lane];
#pragma unroll
        for (int j = 0; j < 32; ++j) {
            float ut = __shfl_sync(0xffffffffu, uv, j);
            h0 = fmaf(a0, h0, ut);
            h1 = fmaf(a1, h1, ut);
            h2 = fmaf(a2, h2, ut);
            h3 = fmaf(a3, h3, ut);
        }
    }
    float* hs = g_hst + (size_t)gw * SS;
    hs[lane]      = h0;
    hs[lane + 32] = h1;
    hs[lane + 64] = h2;
    hs[lane + 96] = h3;
}

// ---------------------------------------------------------------------------
// Kernel 3b: serial prefix-combine over chunks per channel (in-place).
// Slot c becomes the START state H(c); the value combined past c=NC-2 is
// discarded, so reading slot NC-1 (stale) is harmless.
// ---------------------------------------------------------------------------
__global__ __launch_bounds__(128) void combine_kernel()
{
    const int w    = threadIdx.x >> 5;
    const int lane = threadIdx.x & 31;
    const int ch   = blockIdx.x * 4 + w;

    const float p0 = g_A128[lane],      p1 = g_A128[lane + 32],
                p2 = g_A128[lane + 64], p3 = g_A128[lane + 96];

    float H0 = 0.f, H1 = 0.f, H2 = 0.f, H3 = 0.f;
#pragma unroll
    for (int c = 0; c < NC; ++c) {
        float* hs = g_hst + ((size_t)ch * NC + c) * SS;
        float t0 = hs[lane], t1 = hs[lane + 32], t2 = hs[lane + 64], t3 = hs[lane + 96];
        hs[lane]      = H0;
        hs[lane + 32] = H1;
        hs[lane + 64] = H2;
        hs[lane + 96] = H3;
        H0 = fmaf(p0, H0, t0);
        H1 = fmaf(p1, H1, t1);
        H2 = fmaf(p2, H2, t2);
        H3 = fmaf(p3, H3, t3);
    }
}

// ---------------------------------------------------------------------------
// Kernel 3c (pass 2): scan with readout per chunk.
// ---------------------------------------------------------------------------
__global__ __launch_bounds__(128) void lds_kernel(float* __restrict__ out)
{
    __shared__ float ps[4][32 * 33];
    const int w    = threadIdx.x >> 5;
    const int lane = threadIdx.x & 31;
    const int gw   = blockIdx.x * 4 + w;
    const int ch   = gw >> 3;
    const int c    = gw & 7;
    const int b = ch / DD;
    const int d = ch - b * DD;

    const float* uch = g_u + (size_t)ch * TT;
    const float* uc  = uch + c * CL;
    const float a0 = g_A[lane],      a1 = g_A[lane + 32],
                a2 = g_A[lane + 64], a3 = g_A[lane + 96];
    const float* wd = g_wt + d * SS;
    const float w0 = wd[lane],      w1 = wd[lane + 32],
                w2 = wd[lane + 64], w3 = wd[lane + 96];
    const float* gd = g_gd + d * KX;
    const float gd0 = gd[0], gd1 = gd[1], gd2 = gd[2], gd3 = gd[3], gd4 = gd[4];

    const float* hs = g_hst + (size_t)gw * SS;
    float h0 = hs[lane], h1 = hs[lane + 32], h2 = hs[lane + 64], h3 = hs[lane + 96];

    float* psw = ps[w];

#pragma unroll
    for (int r = 0; r < CL / 32; ++r) {
        const int base = r * 32;
        const float uv = uc[base + lane];
#pragma unroll
        for (int j = 0; j < 32; ++j) {
            float ut = __shfl_sync(0xffffffffu, uv, j);
            h0 = fmaf(a0, h0, ut);
            h1 = fmaf(a1, h1, ut);
            h2 = fmaf(a2, h2, ut);
            h3 = fmaf(a3, h3, ut);
            psw[lane * 33 + j] = fmaf(w0, h0, fmaf(w1, h1, fmaf(w2, h2, w3 * h3)));
        }
        __syncwarp();
        float y0 = 0.f, y1 = 0.f, y2 = 0.f, y3 = 0.f;
#pragma unroll
        for (int l = 0; l < 8; ++l) {
            y0 += psw[(l)      * 33 + lane];
            y1 += psw[(l + 8)  * 33 + lane];
            y2 += psw[(l + 16) * 33 + lane];
            y3 += psw[(l + 24) * 33 + lane];
        }
        float y = (y0 + y1) + (y2 + y3);

        const int t = c * CL + base + lane;
        y = fmaf(gd0, uv, y);
        if (t >= 1) y = fmaf(gd1, uch[t - 1], y);
        if (t >= 2) y = fmaf(gd2, uch[t - 2], y);
        if (t >= 3) y = fmaf(gd3, uch[t - 3], y);
        if (t >= 4) y = fmaf(gd4, uch[t - 4], y);

        out[((size_t)b * TT + t) * DD + d] = __bfloat162float(__float2bfloat16(y));
        __syncwarp();
    }
}

// ---------------------------------------------------------------------------
// Launch. Inputs resolved BY ELEMENT COUNT; A/Bm disambiguated by sign.
// Output: float32 (b,T,d) row-major.
// ---------------------------------------------------------------------------
extern "C" void kernel_launch(void* const* d_in, const int* in_sizes, int n_in,
                              void* d_out, int out_size)
{
    const float* x = 0; const float* Mi = 0; const float* Mf = 0;
    const float* v128a = 0; const float* v128b = 0; const float* C = 0;
    const float* Mdir = 0;

    for (int i = 0; i < n_in; ++i) {
        int sz = in_sizes[i];
        const float* p = (const float*)d_in[i];
        if      (sz == BSZ * TT * DD)      x = p;
        else if (sz == DD * DD)            Mi = p;
        else if (sz == KK * DD)            Mf = p;
        else if (sz == 2 * KK * SS)        C = p;
        else if (sz == 2 * KK * KX)        Mdir = p;
        else if (sz == SS) { if (!v128a) v128a = p; else v128b = p; }
    }

    float* out = (float*)d_out;

    resolve_kernel<<<1, SS>>>(v128a, v128b);
    prep_kernel<<<DD, SS>>>(Mf, C, Mdir);
    convert_kernel<<<(MM * DD + 255) / 256, 256>>>(x, Mi);
    gemm_kernel<<<dim3(DD / 64, MM / 64), 256>>>();
    state_kernel<<<NCH * NC / 4, 128>>>();
    combine_kernel<<<NCH / 4, 128>>>();
    lds_kernel<<<NCH * NC / 4, 128>>>(out);
}

// round 16
// speedup vs baseline: 1.0760x; 1.0760x over previous
#include <cuda_runtime.h>
#include <cuda_bf16.h>
#include <mma.h>
#include <stdint.h>

using namespace nvcuda;

// Problem constants
#define BSZ 2
#define TT  1024
#define DD  768
#define KK  24
#define SS  128
#define KX  5
#define NCH (BSZ*DD)   // 1536 channels
#define NC  8          // chunks per channel
#define CL  128        // chunk length (NC*CL == TT)
#define MM  (BSZ*TT)   // 2048 GEMM rows
#define SPLITK 2
#define KHALF (DD / SPLITK)   // 384

// Static device scratch
__device__ float g_u[NCH * TT];          // u[(b*768+d)*1024 + t]
__device__ float g_ua[NCH * TT];         // split-K partial (ks=1)
__device__ float g_wt[DD * SS];          // folded readout weight w~[d][s]
__device__ float g_gd[DD * KX];          // folded direct taps gdir[d][j]
__device__ float g_A[SS];                // resolved decay A
__device__ float g_A128[SS];             // A^CL
__device__ float g_Bm[SS];               // resolved input map Bm
__device__ float g_hst[NCH * NC * SS];   // chunk states
__device__ __nv_bfloat16 g_xh[MM * DD];  // x hi (bf16)
__device__ __nv_bfloat16 g_xl[MM * DD];  // x lo (bf16 residual)
__device__ __nv_bfloat16 g_mh[DD * DD];  // M hi
__device__ __nv_bfloat16 g_ml[DD * DD];  // M lo

// ---------------------------------------------------------------------------
// Kernel 0: resolve A (uniform(0,1): all >= 0) vs Bm (has negatives),
// and precompute A^128 by squaring.
// ---------------------------------------------------------------------------
__global__ void resolve_kernel(const float* __restrict__ p0,
                               const float* __restrict__ p1)
{
    __shared__ int neg0;
    if (threadIdx.x == 0) neg0 = 0;
    __syncthreads();
    if (p0[threadIdx.x] < 0.f) atomicAdd(&neg0, 1);
    __syncthreads();
    const float* Ap = (neg0 > 0) ? p1 : p0;
    const float* Bp = (neg0 > 0) ? p0 : p1;
    float a = Ap[threadIdx.x];
    g_A[threadIdx.x]  = a;
    g_Bm[threadIdx.x] = Bp[threadIdx.x];
    float p = a;
#pragma unroll
    for (int i = 0; i < 7; ++i) p = p * p;   // a^128
    g_A128[threadIdx.x] = p;
}

// ---------------------------------------------------------------------------
// Kernel 1: fold weights.
// ---------------------------------------------------------------------------
__global__ void prep_kernel(const float* __restrict__ Mf,    // (24,768)
                            const float* __restrict__ C,     // (48,128)
                            const float* __restrict__ Mdir)  // (48,5)
{
    int d = blockIdx.x;
    int s = threadIdx.x;
    float acc = 0.f;
#pragma unroll
    for (int k = 0; k < KK; ++k) {
        float mf = Mf[k * DD + d];
        acc += mf * (C[k * SS + s] + C[(KK + k) * SS + s]);
    }
    g_wt[d * SS + s] = acc * g_Bm[s];
    if (s < KX) {
        float a = 0.f;
#pragma unroll
        for (int k = 0; k < KK; ++k) {
            float mf = Mf[k * DD + d];
            a += mf * (Mdir[k * KX + s] + Mdir[(KK + k) * KX + s]);
        }
        g_gd[d * KX + s] = a;
    }
}

// ---------------------------------------------------------------------------
// Kernel 1b: split x and M into bf16 hi + bf16 residual.
// ---------------------------------------------------------------------------
__global__ void convert_kernel(const float* __restrict__ x,
                               const float* __restrict__ M)
{
    int i = blockIdx.x * 256 + threadIdx.x;
    if (i < MM * DD) {
        float v = x[i];
        __nv_bfloat16 h = __float2bfloat16(v);
        g_xh[i] = h;
        g_xl[i] = __float2bfloat16(v - __bfloat162float(h));
    }
    if (i < DD * DD) {
        float v = M[i];
        __nv_bfloat16 h = __float2bfloat16(v);
        g_mh[i] = h;
        g_ml[i] = __float2bfloat16(v - __bfloat162float(h));
    }
}

// ---------------------------------------------------------------------------
// Kernel 2: tensor-core GEMM via WMMA + register prefetch + SPLIT-K(2).
// u[(b,d),t] = sum_c x[m,c]*M[c,d], m = b*1024 + t.
// CTA tile 64m x 64d, BK=32, 4 warps (2m x 2n), warp tile 32x32.
// blockIdx.z = k-split: ks=0 -> g_u (c 0..383), ks=1 -> g_ua (c 384..767).
// Grid 768 CTAs, 3072 warps (~21/SM).
// ASTR=40 (80B rows): conflict-free ldmatrix phases.
// store_matrix_sync(mem_col_major, ldm=TT) writes directly transposed.
// ---------------------------------------------------------------------------
#define ASTR 40     // A smem row stride (bf16 units); 80B, conflict-free
#define BSTR 72     // B smem row stride; 144B, conflict-free

__global__ __launch_bounds__(128) void gemm_kernel()
{
    __shared__ __align__(32) __nv_bfloat16 Ah[64 * ASTR];
    __shared__ __align__(32) __nv_bfloat16 Al[64 * ASTR];
    __shared__ __align__(32) __nv_bfloat16 Bh[32 * BSTR];
    __shared__ __align__(32) __nv_bfloat16 Bl[32 * BSTR];

    const int tid = threadIdx.x;
    const int wid = tid >> 5;
    const int wm  = wid & 1;          // warp m position (2)
    const int wn  = wid >> 1;         // warp n position (2)

    const int m0 = blockIdx.y * 64;   // global row (b*1024 + t)
    const int d0 = blockIdx.x * 64;
    const int ks = blockIdx.z;        // k split
    const int cb = ks * KHALF;        // c base
    float* uout = ks ? g_ua : g_u;

    // per-thread load coordinates (2 chunks per matrix per tile)
    const int ra0 = tid >> 2,          qa0 = tid & 3;
    const int ra1 = (tid + 128) >> 2,  qa1 = tid & 3;
    const int rb0 = tid >> 3,          qb0 = tid & 7;
    const int rb1 = (tid + 128) >> 3,  qb1 = tid & 7;

    wmma::fragment<wmma::accumulator, 16, 16, 16, float> fc[2][2];
#pragma unroll
    for (int i = 0; i < 2; ++i)
#pragma unroll
        for (int j = 0; j < 2; ++j)
            wmma::fill_fragment(fc[i][j], 0.f);

    // prologue: prefetch tile 0
    uint4 pah0, pah1, pal0, pal1, pbh0, pbh1, pbl0, pbl1;
    {
        const size_t a0 = (size_t)(m0 + ra0) * DD + cb + qa0 * 8;
        const size_t a1 = (size_t)(m0 + ra1) * DD + cb + qa1 * 8;
        const size_t b0 = (size_t)(cb + rb0) * DD + d0 + qb0 * 8;
        const size_t b1 = (size_t)(cb + rb1) * DD + d0 + qb1 * 8;
        pah0 = *(const uint4*)&g_xh[a0];  pah1 = *(const uint4*)&g_xh[a1];
        pal0 = *(const uint4*)&g_xl[a0];  pal1 = *(const uint4*)&g_xl[a1];
        pbh0 = *(const uint4*)&g_mh[b0];  pbh1 = *(const uint4*)&g_mh[b1];
        pbl0 = *(const uint4*)&g_ml[b0];  pbl1 = *(const uint4*)&g_ml[b1];
    }

    for (int iter = 0; iter < KHALF / 32; ++iter) {
        // store prefetched tile into smem
        *(uint4*)&Ah[ra0 * ASTR + qa0 * 8] = pah0;
        *(uint4*)&Ah[ra1 * ASTR + qa1 * 8] = pah1;
        *(uint4*)&Al[ra0 * ASTR + qa0 * 8] = pal0;
        *(uint4*)&Al[ra1 * ASTR + qa1 * 8] = pal1;
        *(uint4*)&Bh[rb0 * BSTR + qb0 * 8] = pbh0;
        *(uint4*)&Bh[rb1 * BSTR + qb1 * 8] = pbh1;
        *(uint4*)&Bl[rb0 * BSTR + qb0 * 8] = pbl0;
        *(uint4*)&Bl[rb1 * BSTR + qb1 * 8] = pbl1;
        __syncthreads();

        // prefetch next tile (in flight during compute below)
        if (iter + 1 < KHALF / 32) {
            const int cn = cb + (iter + 1) * 32;
            const size_t a0 = (size_t)(m0 + ra0) * DD + cn + qa0 * 8;
            const size_t a1 = (size_t)(m0 + ra1) * DD + cn + qa1 * 8;
            const size_t b0 = (size_t)(cn + rb0) * DD + d0 + qb0 * 8;
            const size_t b1 = (size_t)(cn + rb1) * DD + d0 + qb1 * 8;
            pah0 = *(const uint4*)&g_xh[a0];  pah1 = *(const uint4*)&g_xh[a1];
            pal0 = *(const uint4*)&g_xl[a0];  pal1 = *(const uint4*)&g_xl[a1];
            pbh0 = *(const uint4*)&g_mh[b0];  pbh1 = *(const uint4*)&g_mh[b1];
            pbl0 = *(const uint4*)&g_ml[b0];  pbl1 = *(const uint4*)&g_ml[b1];
        }

        // compute on current smem tile
#pragma unroll
        for (int kc = 0; kc < 2; ++kc) {
            wmma::fragment<wmma::matrix_a, 16, 16, 16, __nv_bfloat16, wmma::row_major> fah[2], fal[2];
            wmma::fragment<wmma::matrix_b, 16, 16, 16, __nv_bfloat16, wmma::row_major> fbh[2], fbl[2];
#pragma unroll
            for (int i = 0; i < 2; ++i) {
                const __nv_bfloat16* pa = &Ah[(wm * 32 + i * 16) * ASTR + kc * 16];
                const __nv_bfloat16* pl = &Al[(wm * 32 + i * 16) * ASTR + kc * 16];
                wmma::load_matrix_sync(fah[i], pa, ASTR);
                wmma::load_matrix_sync(fal[i], pl, ASTR);
            }
#pragma unroll
            for (int j = 0; j < 2; ++j) {
                const __nv_bfloat16* pb = &Bh[(kc * 16) * BSTR + wn * 32 + j * 16];
                const __nv_bfloat16* pl = &Bl[(kc * 16) * BSTR + wn * 32 + j * 16];
                wmma::load_matrix_sync(fbh[j], pb, BSTR);
                wmma::load_matrix_sync(fbl[j], pl, BSTR);
            }
#pragma unroll
            for (int i = 0; i < 2; ++i)
#pragma unroll
                for (int j = 0; j < 2; ++j) {
                    wmma::mma_sync(fc[i][j], fah[i], fbh[j], fc[i][j]);
                    wmma::mma_sync(fc[i][j], fah[i], fbl[j], fc[i][j]);
                    wmma::mma_sync(fc[i][j], fal[i], fbh[j], fc[i][j]);
                }
        }
        __syncthreads();
    }

    // store transposed: col-major with ldm=TT -> uout[(b*DD + d)*TT + t]
    const int mb = m0 + wm * 32;
    const int b  = mb >> 10;
    const int tb = mb & 1023;
#pragma unroll
    for (int i = 0; i < 2; ++i)
#pragma unroll
        for (int j = 0; j < 2; ++j) {
            int d = d0 + wn * 32 + j * 16;
            float* dst = &uout[((size_t)b * DD + d) * TT + tb + i * 16];
            wmma::store_matrix_sync(dst, fc[i][j], TT, wmma::mem_col_major);
        }
}

// ---------------------------------------------------------------------------
// Kernel 2b: merge split-K partials: g_u += g_ua  (float4, deterministic).
// ---------------------------------------------------------------------------
__global__ __launch_bounds__(256) void addk_kernel()
{
    int i = blockIdx.x * 256 + threadIdx.x;     // float4 index
    float4 a = *(float4*)&g_u[i * 4];
    float4 b = *(float4*)&g_ua[i * 4];
    a.x += b.x; a.y += b.y; a.z += b.z; a.w += b.w;
    *(float4*)&g_u[i * 4] = a;
}

// ---------------------------------------------------------------------------
// Kernel 3a (pass 1): local chunk end-states. Chunk 7's end state unused.
// ---------------------------------------------------------------------------
__global__ __launch_bounds__(128) void state_kernel()
{
    const int w    = threadIdx.x >> 5;
    const int lane = threadIdx.x & 31;
    const int gw   = blockIdx.x * 4 + w;
    const int ch   = gw >> 3;
    const int c    = gw & 7;
    if (c == NC - 1) return;

    const float* uc = g_u + (size_t)ch * TT + c * CL;
    const float a0 = g_A[lane],      a1 = g_A[lane + 32],
                a2 = g_A[lane + 64], a3 = g_A[lane + 96];

    float h0 = 0.f, h1 = 0.f, h2 = 0.f, h3 = 0.f;
#pragma unroll
    for (int r = 0; r < CL / 32; ++r) {
        const float uv = uc[r * 32 + lane];
#pragma unroll
        for (int j = 0; j < 32; ++j) {
            float ut = __shfl_sync(0xffffffffu, uv, j);
            h0 = fmaf(a0, h0, ut);
            h1 = fmaf(a1, h1, ut);
            h2 = fmaf(a2, h2, ut);
            h3 = fmaf(a3, h3, ut);
        }
    }
    float* hs = g_hst + (size_t)gw * SS;
    hs[lane]      = h0;
    hs[lane + 32] = h1;
    hs[lane + 64] = h2;
    hs[lane + 96] = h3;
}

// ---------------------------------------------------------------------------
// Kernel 3b: serial prefix-combine over chunks per channel (in-place).
// ---------------------------------------------------------------------------
__global__ __launch_bounds__(128) void combine_kernel()
{
    const int w    = threadIdx.x >> 5;
    const int lane = threadIdx.x & 31;
    const int ch   = blockIdx.x * 4 + w;

    const float p0 = g_A128[lane],      p1 = g_A128[lane + 32],
                p2 = g_A128[lane + 64], p3 = g_A128[lane + 96];

    float H0 = 0.f, H1 = 0.f, H2 = 0.f, H3 = 0.f;
#pragma unroll
    for (int c = 0; c < NC; ++c) {
        float* hs = g_hst + ((size_t)ch * NC + c) * SS;
        float t0 = hs[lane], t1 = hs[lane + 32], t2 = hs[lane + 64], t3 = hs[lane + 96];
        hs[lane]      = H0;
        hs[lane + 32] = H1;
        hs[lane + 64] = H2;
        hs[lane + 96] = H3;
        H0 = fmaf(p0, H0, t0);
        H1 = fmaf(p1, H1, t1);
        H2 = fmaf(p2, H2, t2);
        H3 = fmaf(p3, H3, t3);
    }
}

// ---------------------------------------------------------------------------
// Kernel 3c (pass 2): scan with readout per chunk.
// ---------------------------------------------------------------------------
__global__ __launch_bounds__(128) void lds_kernel(float* __restrict__ out)
{
    __shared__ float ps[4][32 * 33];
    const int w    = threadIdx.x >> 5;
    const int lane = threadIdx.x & 31;
    const int gw   = blockIdx.x * 4 + w;
    const int ch   = gw >> 3;
    const int c    = gw & 7;
    const int b = ch / DD;
    const int d = ch - b * DD;

    const float* uch = g_u + (size_t)ch * TT;
    const float* uc  = uch + c * CL;
    const float a0 = g_A[lane],      a1 = g_A[lane + 32],
                a2 = g_A[lane + 64], a3 = g_A[lane + 96];
    const float* wd = g_wt + d * SS;
    const float w0 = wd[lane],      w1 = wd[lane + 32],
                w2 = wd[lane + 64], w3 = wd[lane + 96];
    const float* gd = g_gd + d * KX;
    const float gd0 = gd[0], gd1 = gd[1], gd2 = gd[2], gd3 = gd[3], gd4 = gd[4];

    const float* hs = g_hst + (size_t)gw * SS;
    float h0 = hs[lane], h1 = hs[lane + 32], h2 = hs[lane + 64], h3 = hs[lane + 96];

    float* psw = ps[w];

#pragma unroll
    for (int r = 0; r < CL / 32; ++r) {
        const int base = r * 32;
        const float uv = uc[base + lane];
#pragma unroll
        for (int j = 0; j < 32; ++j) {
            float ut = __shfl_sync(0xffffffffu, uv, j);
            h0 = fmaf(a0, h0, ut);
            h1 = fmaf(a1, h1, ut);
            h2 = fmaf(a2, h2, ut);
            h3 = fmaf(a3, h3, ut);
            psw[lane * 33 + j] = fmaf(w0, h0, fmaf(w1, h1, fmaf(w2, h2, w3 * h3)));
        }
        __syncwarp();
        float y0 = 0.f, y1 = 0.f, y2 = 0.f, y3 = 0.f;
#pragma unroll
        for (int l = 0; l < 8; ++l) {
            y0 += psw[(l)      * 33 + lane];
            y1 += psw[(l + 8)  * 33 + lane];
            y2 += psw[(l + 16) * 33 + lane];
            y3 += psw[(l + 24) * 33 + lane];
        }
        float y = (y0 + y1) + (y2 + y3);

        const int t = c * CL + base + lane;
        y = fmaf(gd0, uv, y);
        if (t >= 1) y = fmaf(gd1, uch[t - 1], y);
        if (t >= 2) y = fmaf(gd2, uch[t - 2], y);
        if (t >= 3) y = fmaf(gd3, uch[t - 3], y);
        if (t >= 4) y = fmaf(gd4, uch[t - 4], y);

        out[((size_t)b * TT + t) * DD + d] = __bfloat162float(__float2bfloat16(y));
        __syncwarp();
    }
}

// ---------------------------------------------------------------------------
// Launch. Inputs resolved BY ELEMENT COUNT; A/Bm disambiguated by sign.
// Output: float32 (b,T,d) row-major.
// ---------------------------------------------------------------------------
extern "C" void kernel_launch(void* const* d_in, const int* in_sizes, int n_in,
                              void* d_out, int out_size)
{
    const float* x = 0; const float* Mi = 0; const float* Mf = 0;
    const float* v128a = 0; const float* v128b = 0; const float* C = 0;
    const float* Mdir = 0;

    for (int i = 0; i < n_in; ++i) {
        int sz = in_sizes[i];
        const float* p = (const float*)d_in[i];
        if      (sz == BSZ * TT * DD)      x = p;
        else if (sz == DD * DD)            Mi = p;
        else if (sz == KK * DD)            Mf = p;
        else if (sz == 2 * KK * SS)        C = p;
        else if (sz == 2 * KK * KX)        Mdir = p;
        else if (sz == SS) { if (!v128a) v128a = p; else v128b = p; }
    }

    float* out = (float*)d_out;

    resolve_kernel<<<1, SS>>>(v128a, v128b);
    prep_kernel<<<DD, SS>>>(Mf, C, Mdir);
    convert_kernel<<<(MM * DD + 255) / 256, 256>>>(x, Mi);
    gemm_kernel<<<dim3(DD / 64, MM / 64, SPLITK), 128>>>();
    addk_kernel<<<NCH * TT / 4 / 256, 256>>>();
    state_kernel<<<NCH * NC / 4, 128>>>();
    combine_kernel<<<NCH / 4, 128>>>();
    lds_kernel<<<NCH * NC / 4, 128>>>(out);
}